// round 14
// baseline (speedup 1.0000x reference)
#include <cuda_runtime.h>
#include <cuda_fp16.h>
#include <math.h>

#define NN 100000
#define NE 1600000
#define ET (NE + NN)
#define DH 64
#define NG 64
#define NB_SCAN 98   // ceil(NN/1024)
#define XST 72       // padded smem row stride (halves) -> conflict-free frags

// ---- scratch (device globals) ----
__device__ __align__(16) __half2 g_h2[NN * 32];   // projected features (fp16)
__device__ __align__(16) __half2 g_x2[NN * 32];   // activated layer output (fp16)
__device__ float g_s[NN];                         // h . a_src per node
__device__ float g_d[NN];                         // h . a_dst per node
__device__ float g_vn[NG * DH];                   // pooled virtual-node features
__device__ int   g_cnt[NN];                       // in-degree (incl. self loop)
__device__ int   g_row[NN + 1];                   // CSR row offsets (by dst)
__device__ int   g_woff[NN];                      // working offsets for scatter
__device__ int   g_csrc[ET];                      // CSR: src node per edge slot
__device__ int   g_bsum[128];

// ===========================================================================
// CSR build (edge_index constant across layers -> build once per launch)
// ===========================================================================
__global__ void k_initcnt(const float* __restrict__ emb) {
    int i = blockIdx.x * blockDim.x + threadIdx.x;
    if (i < NN) g_cnt[i] = 1;  // self loop
    if (i < NG * DH) g_vn[i] = emb[i & 63];  // virtual-node init (fused)
}

__global__ void k_hist(const int* __restrict__ ei) {
    int i = blockIdx.x * blockDim.x + threadIdx.x;
    if (i < NE) atomicAdd(&g_cnt[ei[NE + i]], 1);
}

// warp-shuffle block scan (1024 threads)
__global__ void k_scan1() {
    __shared__ int wsum[32];
    int t = threadIdx.x;
    int idx = blockIdx.x * 1024 + t;
    int v = (idx < NN) ? g_cnt[idx] : 0;
    int lane = t & 31, wid = t >> 5;
    int sc = v;
#pragma unroll
    for (int o = 1; o < 32; o <<= 1) {
        int nv = __shfl_up_sync(0xffffffffu, sc, o);
        if (lane >= o) sc += nv;
    }
    if (lane == 31) wsum[wid] = sc;
    __syncthreads();
    if (wid == 0) {
        int wv = wsum[lane];
        int ws = wv;
#pragma unroll
        for (int o = 1; o < 32; o <<= 1) {
            int nv = __shfl_up_sync(0xffffffffu, ws, o);
            if (lane >= o) ws += nv;
        }
        wsum[lane] = ws - wv;  // exclusive
    }
    __syncthreads();
    int incl = sc + wsum[wid];
    if (idx < NN) g_row[idx] = incl - v;
    if (t == 1023) g_bsum[blockIdx.x] = incl;
}

__global__ void k_scan3() {
    __shared__ int sb[128];
    int t = threadIdx.x;
    if (t < 128) sb[t] = (t < NB_SCAN) ? g_bsum[t] : 0;
    __syncthreads();
#pragma unroll
    for (int o = 1; o < 128; o <<= 1) {
        int nv = (t >= o && t < 128) ? sb[t - o] : 0;
        __syncthreads();
        if (t < 128) sb[t] += nv;
        __syncthreads();
    }
    int idx = blockIdx.x * blockDim.x + t;
    if (idx < NN) {
        int blk = idx >> 10;
        int r = g_row[idx] + (blk ? sb[blk - 1] : 0);
        g_row[idx] = r;
        g_woff[idx] = r;
    }
    if (idx == 0) g_row[NN] = ET;
}

__global__ void k_scatter(const int* __restrict__ ei) {
    int i = blockIdx.x * blockDim.x + threadIdx.x;
    if (i >= ET) return;
    int s, d;
    if (i < NE) { s = ei[i]; d = ei[NE + i]; }
    else        { s = d = i - NE; }
    int pos = atomicAdd(&g_woff[d], 1);
    g_csrc[pos] = s;
}

// ===========================================================================
// Tensor-core matmul: 256 nodes / 512-thread block; conflict-free padded smem.
// ===========================================================================
__global__ void __launch_bounds__(512) k_mm(
        const void* __restrict__ xin, int inHalf, const float* __restrict__ W,
        const float* __restrict__ bias, float* __restrict__ dstF, int writeH,
        const float* __restrict__ a_src, const float* __restrict__ a_dst) {
    __shared__ __align__(16) __half xs[256 * XST];   // 36 KB
    __shared__ __align__(16) __half Wt[64 * XST];    // 9 KB
    __shared__ float sbias[64], sas[64], sad[64];
    int t = threadIdx.x;
    if (t < 64) {
        sbias[t] = bias  ? bias[t]  : 0.f;
        sas[t]   = a_src ? a_src[t] : 0.f;
        sad[t]   = a_dst ? a_dst[t] : 0.f;
    }
    const float4* W4 = (const float4*)W;
    for (int i4 = t; i4 < 1024; i4 += 512) {
        float4 wv = W4[i4];
        int k = i4 >> 4;
        int n0 = (i4 & 15) * 4;
        Wt[(n0 + 0) * XST + k] = __float2half(wv.x);
        Wt[(n0 + 1) * XST + k] = __float2half(wv.y);
        Wt[(n0 + 2) * XST + k] = __float2half(wv.z);
        Wt[(n0 + 3) * XST + k] = __float2half(wv.w);
    }
    int base = blockIdx.x * 256;
    if (inHalf) {
        const uint2* xh = (const uint2*)xin;
        for (int i4 = t; i4 < 4096; i4 += 512) {
            int g4 = base * 16 + i4;
            uint2 v = (g4 < NN * 16) ? __ldg(&xh[g4]) : make_uint2(0u, 0u);
            int node = i4 >> 4, c = i4 & 15;
            *(uint2*)&xs[node * XST + c * 4] = v;
        }
    } else {
        const float4* x4 = (const float4*)xin;
        for (int i4 = t; i4 < 4096; i4 += 512) {
            int g4 = base * 16 + i4;
            float4 v = (g4 < NN * 16) ? x4[g4] : make_float4(0.f, 0.f, 0.f, 0.f);
            int node = i4 >> 4, c = i4 & 15;
            __half2* d2 = (__half2*)&xs[node * XST + c * 4];
            d2[0] = __floats2half2_rn(v.x, v.y);
            d2[1] = __floats2half2_rn(v.z, v.w);
        }
    }
    __syncthreads();

    int w = t >> 5, l = t & 31;
    int gr = l >> 2, q = l & 3;
    int lrow = w * 16 + gr;      // local row in [0,256)

    float acc[8][4];
#pragma unroll
    for (int i = 0; i < 8; i++)
#pragma unroll
        for (int j = 0; j < 4; j++) acc[i][j] = 0.f;

    const unsigned* xsu = (const unsigned*)xs;
    const unsigned* wtu = (const unsigned*)Wt;
#pragma unroll
    for (int kk = 0; kk < 4; kk++) {
        int k0 = 16 * kk + 2 * q;
        unsigned a0 = xsu[(lrow * XST + k0) >> 1];
        unsigned a1 = xsu[((lrow + 8) * XST + k0) >> 1];
        unsigned a2 = xsu[(lrow * XST + k0 + 8) >> 1];
        unsigned a3 = xsu[((lrow + 8) * XST + k0 + 8) >> 1];
#pragma unroll
        for (int tt = 0; tt < 8; tt++) {
            int n = tt * 8 + gr;
            unsigned b0 = wtu[(n * XST + k0) >> 1];
            unsigned b1 = wtu[(n * XST + k0 + 8) >> 1];
            asm("mma.sync.aligned.m16n8k16.row.col.f32.f16.f16.f32 "
                "{%0,%1,%2,%3}, {%4,%5,%6,%7}, {%8,%9}, {%0,%1,%2,%3};"
                : "+f"(acc[tt][0]), "+f"(acc[tt][1]),
                  "+f"(acc[tt][2]), "+f"(acc[tt][3])
                : "r"(a0), "r"(a1), "r"(a2), "r"(a3), "r"(b0), "r"(b1));
        }
    }

    int n0 = base + lrow, n1 = n0 + 8;
    float s0 = 0.f, s1 = 0.f, d0s = 0.f, d1s = 0.f;
#pragma unroll
    for (int tt = 0; tt < 8; tt++) {
        int c0 = tt * 8 + 2 * q;
        float2 bv = *(float2*)&sbias[c0];
        float v00 = acc[tt][0] + bv.x, v01 = acc[tt][1] + bv.y;
        float v10 = acc[tt][2] + bv.x, v11 = acc[tt][3] + bv.y;
        if (writeH) {
            if (n0 < NN) g_h2[(size_t)n0 * 32 + tt * 4 + q] = __floats2half2_rn(v00, v01);
            if (n1 < NN) g_h2[(size_t)n1 * 32 + tt * 4 + q] = __floats2half2_rn(v10, v11);
        }
        if (dstF) {
            if (n0 < NN) *(float2*)&dstF[(size_t)n0 * 64 + c0] = make_float2(v00, v01);
            if (n1 < NN) *(float2*)&dstF[(size_t)n1 * 64 + c0] = make_float2(v10, v11);
        }
        if (a_src) {
            float2 asv = *(float2*)&sas[c0];
            float2 adv = *(float2*)&sad[c0];
            s0  += v00 * asv.x + v01 * asv.y;
            s1  += v10 * asv.x + v11 * asv.y;
            d0s += v00 * adv.x + v01 * adv.y;
            d1s += v10 * adv.x + v11 * adv.y;
        }
    }
    if (a_src) {
#pragma unroll
        for (int o = 1; o <= 2; o <<= 1) {
            s0  += __shfl_xor_sync(0xffffffffu, s0, o);
            s1  += __shfl_xor_sync(0xffffffffu, s1, o);
            d0s += __shfl_xor_sync(0xffffffffu, d0s, o);
            d1s += __shfl_xor_sync(0xffffffffu, d1s, o);
        }
        if (q == 0) {
            if (n0 < NN) { g_s[n0] = s0; g_d[n0] = d0s; }
            if (n1 < NN) { g_s[n1] = s1; g_d[n1] = d1s; }
        }
    }
}

// ===========================================================================
// Fused GAT softmax + aggregation; shift-free softmax; 2 nodes/warp;
// 8-edge batches with cross-batch csrc prefetch (shadow registers).
// ===========================================================================
__device__ __forceinline__ float edge_p(int src, float dval) {
    float e = __ldg(&g_s[src]) + dval;
    e = fmaxf(e, 0.2f * e);          // leaky_relu(0.2)
    return __expf(fminf(e, 60.f));
}

__global__ void __launch_bounds__(256, 4) k_agg(const float* __restrict__ bias,
                                                __half2* __restrict__ outp) {
    int w = threadIdx.x >> 5, lane = threadIdx.x & 31;
    int half = lane >> 4, hl = lane & 15;
    int n = blockIdx.x * 16 + w * 2 + half;
    bool valid = n < NN;
    int rs = valid ? g_row[n] : 0;
    int deg = valid ? g_row[n + 1] - rs : 0;
    float dval = valid ? g_d[n] : 0.f;

    float s = 0.f, a0 = 0.f, a1 = 0.f, a2 = 0.f, a3 = 0.f;
    const uint2* __restrict__ h2p = (const uint2*)g_h2;

    int j = 0;
    if (8 <= deg) {
        int s_[8];
#pragma unroll
        for (int u = 0; u < 8; u++) s_[u] = __ldg(&g_csrc[rs + u]);
        while (true) {
            uint2 h_[8]; float p_[8];
#pragma unroll
            for (int u = 0; u < 8; u++) h_[u] = __ldg(&h2p[s_[u] * 16 + hl]);
#pragma unroll
            for (int u = 0; u < 8; u++) p_[u] = edge_p(s_[u], dval);
            int jn = j + 8;
            bool more = (jn + 8 <= deg);
            if (more) {
#pragma unroll
                for (int u = 0; u < 8; u++) s_[u] = __ldg(&g_csrc[rs + jn + u]);
            }
#pragma unroll
            for (int u = 0; u < 8; u++) {
                s += p_[u];
                float2 fa = __half22float2(*(__half2*)&h_[u].x);
                float2 fb = __half22float2(*(__half2*)&h_[u].y);
                a0 = fmaf(p_[u], fa.x, a0); a1 = fmaf(p_[u], fa.y, a1);
                a2 = fmaf(p_[u], fb.x, a2); a3 = fmaf(p_[u], fb.y, a3);
            }
            j = jn;
            if (!more) break;
        }
    }
    for (; j < deg; j++) {
        int s0 = __ldg(&g_csrc[rs + j]);
        float p0 = edge_p(s0, dval);
        uint2 h0 = __ldg(&h2p[s0 * 16 + hl]);
        s += p0;
        float2 fa = __half22float2(*(__half2*)&h0.x);
        float2 fb = __half22float2(*(__half2*)&h0.y);
        a0 = fmaf(p0, fa.x, a0); a1 = fmaf(p0, fa.y, a1);
        a2 = fmaf(p0, fb.x, a2); a3 = fmaf(p0, fb.y, a3);
    }

    if (!valid) return;
    float inv = 1.f / (s + 1e-16f);
    float4 b4 = *(const float4*)&bias[4 * hl];
    float v0 = fmaf(a0, inv, b4.x);
    float v1 = fmaf(a1, inv, b4.y);
    float v2 = fmaf(a2, inv, b4.z);
    float v3 = fmaf(a3, inv, b4.w);
    v0 = v0 > 0.f ? v0 : 0.01f * v0;
    v1 = v1 > 0.f ? v1 : 0.01f * v1;
    v2 = v2 > 0.f ? v2 : 0.01f * v2;
    v3 = v3 > 0.f ? v3 : 0.01f * v3;
    __half2 o0 = __floats2half2_rn(v0, v1);
    __half2 o1 = __floats2half2_rn(v2, v3);
    uint2 pack = make_uint2(*(unsigned*)&o0, *(unsigned*)&o1);
    *(uint2*)&outp[(size_t)n * 32 + 2 * hl] = pack;
}

// ---- virtual node pool: 256 threads = 4 groups x 64 cols, 64 nodes/group ----
__global__ void k_pool(const int* __restrict__ batch) {
    int c = threadIdx.x & 63;
    int grp = threadIdx.x >> 6;
    int n0 = blockIdx.x * 256 + grp * 64;
    int n1 = n0 + 64; if (n1 > NN) n1 = NN;
    if (n0 >= NN) return;
    const __half* xp = (const __half*)g_x2;
    float acc = 0.f;
    int cur = batch[n0];
    for (int n = n0; n < n1; n++) {
        int bb = batch[n];
        if (bb != cur) { atomicAdd(&g_vn[cur * DH + c], acc); acc = 0.f; cur = bb; }
        acc += __half2float(xp[(size_t)n * DH + c]);
    }
    atomicAdd(&g_vn[cur * DH + c], acc);
}

// ---- 4-layer MLP on vn, one block (64 threads) per graph ----
__global__ void k_vnmlp(const float* __restrict__ W1, const float* __restrict__ b1,
                        const float* __restrict__ W2, const float* __restrict__ b2,
                        const float* __restrict__ W3, const float* __restrict__ b3,
                        const float* __restrict__ W4, const float* __restrict__ b4,
                        float* __restrict__ outp) {
    __shared__ float r[64];
    int g = blockIdx.x, c = threadIdx.x;
    r[c] = g_vn[g * DH + c];
    __syncthreads();
    const float* Ws[4] = {W1, W2, W3, W4};
    const float* bs[4] = {b1, b2, b3, b4};
    for (int L = 0; L < 4; L++) {
        float acc = bs[L][c];
        for (int k = 0; k < 64; k++) acc = fmaf(r[k], Ws[L][k * 64 + c], acc);
        __syncthreads();
        r[c] = acc > 0.f ? acc : 0.f;
        __syncthreads();
    }
    outp[g * DH + c] = r[c];
}

extern "C" void kernel_launch(void* const* d_in, const int* in_sizes, int n_in,
                              void* d_out, int out_size) {
    const float* x     = (const float*)d_in[0];
    const int*   ei    = (const int*)d_in[1];
    const int*   batch = (const int*)d_in[2];
    int o = (in_sizes[3] <= 16) ? 4 : 3;
    const float* W[3], *asr[3], *adt[3], *bb[3];
    for (int i = 0; i < 3; i++) {
        W[i]   = (const float*)d_in[o + 4 * i + 0];
        asr[i] = (const float*)d_in[o + 4 * i + 1];
        adt[i] = (const float*)d_in[o + 4 * i + 2];
        bb[i]  = (const float*)d_in[o + 4 * i + 3];
    }
    const float* Wout = (const float*)d_in[o + 12];
    const float* bout = (const float*)d_in[o + 13];
    const float* vne  = (const float*)d_in[o + 14];
    const float* Wm1 = (const float*)d_in[o + 15], *bm1 = (const float*)d_in[o + 16];
    const float* Wm2 = (const float*)d_in[o + 17], *bm2 = (const float*)d_in[o + 18];
    const float* Wf1 = (const float*)d_in[o + 19], *bf1 = (const float*)d_in[o + 20];
    const float* Wf2 = (const float*)d_in[o + 21], *bf2 = (const float*)d_in[o + 22];

    __half2* px2 = nullptr;
    cudaGetSymbolAddress((void**)&px2, g_x2);
    float* out = (float*)d_out;

    // ---- CSR build (once; reused by all 3 layers) ----
    k_initcnt<<<(NN + 255) / 256, 256>>>(vne);
    k_hist<<<(NE + 255) / 256, 256>>>(ei);
    k_scan1<<<NB_SCAN, 1024>>>();
    k_scan3<<<(NN + 255) / 256, 256>>>();
    k_scatter<<<(ET + 255) / 256, 256>>>(ei);

    // ---- 3 GAT layers ----
    for (int L = 0; L < 3; L++) {
        const void* cur = (L == 0) ? (const void*)x : (const void*)px2;
        k_mm<<<(NN + 255) / 256, 512>>>(cur, L != 0, W[L], nullptr, nullptr, 1,
                                        asr[L], adt[L]);
        k_agg<<<(NN + 15) / 16, 256>>>(bb[L], px2);
    }

    // final node projection (fp32 out, with bias)
    k_mm<<<(NN + 255) / 256, 512>>>(px2, 1, Wout, bout, out, 0, nullptr, nullptr);

    // virtual node branch
    k_pool<<<(NN + 255) / 256, 256>>>(batch);
    k_vnmlp<<<NG, 64>>>(Wm1, bm1, Wm2, bm2, Wf1, bf1, Wf2, bf2, out + (size_t)NN * DH);
}

// round 15
// speedup vs baseline: 1.1110x; 1.1110x over previous
#include <cuda_runtime.h>
#include <cuda_fp16.h>
#include <math.h>

#define NN 100000
#define NE 1600000
#define ET (NE + NN)
#define DH 64
#define NG 64
#define NB_SCAN 98   // ceil(NN/1024)
#define XST 72       // padded smem row stride (halves) -> conflict-free frags

// ---- scratch (device globals) ----
__device__ __align__(16) __half2 g_h2[NN * 32];   // projected features (fp16)
__device__ __align__(16) __half2 g_x2[NN * 32];   // activated layer output (fp16)
__device__ float g_s[NN];                         // h . a_src per node
__device__ float g_d[NN];                         // h . a_dst per node
__device__ float g_vn[NG * DH];                   // pooled virtual-node features
__device__ int   g_cnt[NN];                       // in-degree (incl. self loop)
__device__ int   g_row[NN + 1];                   // CSR row offsets (by dst)
__device__ int   g_woff[NN];                      // working offsets for scatter
__device__ int   g_csrc[ET];                      // CSR: src node per edge slot
__device__ int   g_bsum[128];

// ===========================================================================
// CSR build (edge_index constant across layers -> build once per launch)
// ===========================================================================
__global__ void k_initcnt(const float* __restrict__ emb) {
    int i = blockIdx.x * blockDim.x + threadIdx.x;
    if (i < NN) g_cnt[i] = 1;  // self loop
    if (i < NG * DH) g_vn[i] = emb[i & 63];  // virtual-node init (fused)
}

__global__ void k_hist(const int* __restrict__ ei) {
    int i = blockIdx.x * blockDim.x + threadIdx.x;
    if (i < NE) atomicAdd(&g_cnt[ei[NE + i]], 1);
}

// warp-shuffle block scan (1024 threads)
__global__ void k_scan1() {
    __shared__ int wsum[32];
    int t = threadIdx.x;
    int idx = blockIdx.x * 1024 + t;
    int v = (idx < NN) ? g_cnt[idx] : 0;
    int lane = t & 31, wid = t >> 5;
    int sc = v;
#pragma unroll
    for (int o = 1; o < 32; o <<= 1) {
        int nv = __shfl_up_sync(0xffffffffu, sc, o);
        if (lane >= o) sc += nv;
    }
    if (lane == 31) wsum[wid] = sc;
    __syncthreads();
    if (wid == 0) {
        int wv = wsum[lane];
        int ws = wv;
#pragma unroll
        for (int o = 1; o < 32; o <<= 1) {
            int nv = __shfl_up_sync(0xffffffffu, ws, o);
            if (lane >= o) ws += nv;
        }
        wsum[lane] = ws - wv;  // exclusive
    }
    __syncthreads();
    int incl = sc + wsum[wid];
    if (idx < NN) g_row[idx] = incl - v;
    if (t == 1023) g_bsum[blockIdx.x] = incl;
}

__global__ void k_scan3() {
    __shared__ int sb[128];
    int t = threadIdx.x;
    if (t < 128) sb[t] = (t < NB_SCAN) ? g_bsum[t] : 0;
    __syncthreads();
#pragma unroll
    for (int o = 1; o < 128; o <<= 1) {
        int nv = (t >= o && t < 128) ? sb[t - o] : 0;
        __syncthreads();
        if (t < 128) sb[t] += nv;
        __syncthreads();
    }
    int idx = blockIdx.x * blockDim.x + t;
    if (idx < NN) {
        int blk = idx >> 10;
        int r = g_row[idx] + (blk ? sb[blk - 1] : 0);
        g_row[idx] = r;
        g_woff[idx] = r;
    }
    if (idx == 0) g_row[NN] = ET;
}

__global__ void k_scatter(const int* __restrict__ ei) {
    int i = blockIdx.x * blockDim.x + threadIdx.x;
    if (i >= ET) return;
    int s, d;
    if (i < NE) { s = ei[i]; d = ei[NE + i]; }
    else        { s = d = i - NE; }
    int pos = atomicAdd(&g_woff[d], 1);
    g_csrc[pos] = s;
}

// ===========================================================================
// Tensor-core matmul: 256 nodes / 512-thread block; conflict-free padded smem.
// ===========================================================================
__global__ void __launch_bounds__(512) k_mm(
        const void* __restrict__ xin, int inHalf, const float* __restrict__ W,
        const float* __restrict__ bias, float* __restrict__ dstF, int writeH,
        const float* __restrict__ a_src, const float* __restrict__ a_dst) {
    __shared__ __align__(16) __half xs[256 * XST];   // 36 KB
    __shared__ __align__(16) __half Wt[64 * XST];    // 9 KB
    __shared__ float sbias[64], sas[64], sad[64];
    int t = threadIdx.x;
    if (t < 64) {
        sbias[t] = bias  ? bias[t]  : 0.f;
        sas[t]   = a_src ? a_src[t] : 0.f;
        sad[t]   = a_dst ? a_dst[t] : 0.f;
    }
    const float4* W4 = (const float4*)W;
    for (int i4 = t; i4 < 1024; i4 += 512) {
        float4 wv = W4[i4];
        int k = i4 >> 4;
        int n0 = (i4 & 15) * 4;
        Wt[(n0 + 0) * XST + k] = __float2half(wv.x);
        Wt[(n0 + 1) * XST + k] = __float2half(wv.y);
        Wt[(n0 + 2) * XST + k] = __float2half(wv.z);
        Wt[(n0 + 3) * XST + k] = __float2half(wv.w);
    }
    int base = blockIdx.x * 256;
    if (inHalf) {
        const uint2* xh = (const uint2*)xin;
        for (int i4 = t; i4 < 4096; i4 += 512) {
            int g4 = base * 16 + i4;
            uint2 v = (g4 < NN * 16) ? __ldg(&xh[g4]) : make_uint2(0u, 0u);
            int node = i4 >> 4, c = i4 & 15;
            *(uint2*)&xs[node * XST + c * 4] = v;
        }
    } else {
        const float4* x4 = (const float4*)xin;
        for (int i4 = t; i4 < 4096; i4 += 512) {
            int g4 = base * 16 + i4;
            float4 v = (g4 < NN * 16) ? x4[g4] : make_float4(0.f, 0.f, 0.f, 0.f);
            int node = i4 >> 4, c = i4 & 15;
            __half2* d2 = (__half2*)&xs[node * XST + c * 4];
            d2[0] = __floats2half2_rn(v.x, v.y);
            d2[1] = __floats2half2_rn(v.z, v.w);
        }
    }
    __syncthreads();

    int w = t >> 5, l = t & 31;
    int gr = l >> 2, q = l & 3;
    int lrow = w * 16 + gr;      // local row in [0,256)

    float acc[8][4];
#pragma unroll
    for (int i = 0; i < 8; i++)
#pragma unroll
        for (int j = 0; j < 4; j++) acc[i][j] = 0.f;

    const unsigned* xsu = (const unsigned*)xs;
    const unsigned* wtu = (const unsigned*)Wt;
#pragma unroll
    for (int kk = 0; kk < 4; kk++) {
        int k0 = 16 * kk + 2 * q;
        unsigned a0 = xsu[(lrow * XST + k0) >> 1];
        unsigned a1 = xsu[((lrow + 8) * XST + k0) >> 1];
        unsigned a2 = xsu[(lrow * XST + k0 + 8) >> 1];
        unsigned a3 = xsu[((lrow + 8) * XST + k0 + 8) >> 1];
#pragma unroll
        for (int tt = 0; tt < 8; tt++) {
            int n = tt * 8 + gr;
            unsigned b0 = wtu[(n * XST + k0) >> 1];
            unsigned b1 = wtu[(n * XST + k0 + 8) >> 1];
            asm("mma.sync.aligned.m16n8k16.row.col.f32.f16.f16.f32 "
                "{%0,%1,%2,%3}, {%4,%5,%6,%7}, {%8,%9}, {%0,%1,%2,%3};"
                : "+f"(acc[tt][0]), "+f"(acc[tt][1]),
                  "+f"(acc[tt][2]), "+f"(acc[tt][3])
                : "r"(a0), "r"(a1), "r"(a2), "r"(a3), "r"(b0), "r"(b1));
        }
    }

    int n0 = base + lrow, n1 = n0 + 8;
    float s0 = 0.f, s1 = 0.f, d0s = 0.f, d1s = 0.f;
#pragma unroll
    for (int tt = 0; tt < 8; tt++) {
        int c0 = tt * 8 + 2 * q;
        float2 bv = *(float2*)&sbias[c0];
        float v00 = acc[tt][0] + bv.x, v01 = acc[tt][1] + bv.y;
        float v10 = acc[tt][2] + bv.x, v11 = acc[tt][3] + bv.y;
        if (writeH) {
            if (n0 < NN) g_h2[(size_t)n0 * 32 + tt * 4 + q] = __floats2half2_rn(v00, v01);
            if (n1 < NN) g_h2[(size_t)n1 * 32 + tt * 4 + q] = __floats2half2_rn(v10, v11);
        }
        if (dstF) {
            if (n0 < NN) *(float2*)&dstF[(size_t)n0 * 64 + c0] = make_float2(v00, v01);
            if (n1 < NN) *(float2*)&dstF[(size_t)n1 * 64 + c0] = make_float2(v10, v11);
        }
        if (a_src) {
            float2 asv = *(float2*)&sas[c0];
            float2 adv = *(float2*)&sad[c0];
            s0  += v00 * asv.x + v01 * asv.y;
            s1  += v10 * asv.x + v11 * asv.y;
            d0s += v00 * adv.x + v01 * adv.y;
            d1s += v10 * adv.x + v11 * adv.y;
        }
    }
    if (a_src) {
#pragma unroll
        for (int o = 1; o <= 2; o <<= 1) {
            s0  += __shfl_xor_sync(0xffffffffu, s0, o);
            s1  += __shfl_xor_sync(0xffffffffu, s1, o);
            d0s += __shfl_xor_sync(0xffffffffu, d0s, o);
            d1s += __shfl_xor_sync(0xffffffffu, d1s, o);
        }
        if (q == 0) {
            if (n0 < NN) { g_s[n0] = s0; g_d[n0] = d0s; }
            if (n1 < NN) { g_s[n1] = s1; g_d[n1] = d1s; }
        }
    }
}

// ===========================================================================
// Fused GAT softmax + aggregation; shift-free softmax.
// FOUR nodes per warp: 8 lanes per node, 8 cols (one uint4) per lane.
// Each 8-lane group owns its node end-to-end (no shuffle merge).
// ===========================================================================
__device__ __forceinline__ float edge_p(int src, float dval) {
    float e = __ldg(&g_s[src]) + dval;
    e = fmaxf(e, 0.2f * e);          // leaky_relu(0.2)
    return __expf(fminf(e, 60.f));
}

__global__ void __launch_bounds__(256, 4) k_agg(const float* __restrict__ bias,
                                                __half2* __restrict__ outp) {
    int w = threadIdx.x >> 5, lane = threadIdx.x & 31;
    int g = lane >> 3, r = lane & 7;
    int n = blockIdx.x * 32 + w * 4 + g;
    bool valid = n < NN;
    int rs = valid ? g_row[n] : 0;
    int deg = valid ? g_row[n + 1] - rs : 0;
    float dval = valid ? g_d[n] : 0.f;

    float s = 0.f;
    float a0 = 0.f, a1 = 0.f, a2 = 0.f, a3 = 0.f;
    float a4 = 0.f, a5 = 0.f, a6 = 0.f, a7 = 0.f;
    const uint4* __restrict__ hp = (const uint4*)g_h2;  // 8 uint4 per row

    int j = 0;
    for (; j + 4 <= deg; j += 4) {
        int s0 = __ldg(&g_csrc[rs + j]);
        int s1 = __ldg(&g_csrc[rs + j + 1]);
        int s2 = __ldg(&g_csrc[rs + j + 2]);
        int s3 = __ldg(&g_csrc[rs + j + 3]);
        uint4 h0 = __ldg(&hp[s0 * 8 + r]);
        uint4 h1 = __ldg(&hp[s1 * 8 + r]);
        uint4 h2 = __ldg(&hp[s2 * 8 + r]);
        uint4 h3 = __ldg(&hp[s3 * 8 + r]);
        float p0 = edge_p(s0, dval), p1 = edge_p(s1, dval);
        float p2 = edge_p(s2, dval), p3 = edge_p(s3, dval);
        s += (p0 + p1) + (p2 + p3);
        float2 f;
        f = __half22float2(*(__half2*)&h0.x); a0 = fmaf(p0, f.x, a0); a1 = fmaf(p0, f.y, a1);
        f = __half22float2(*(__half2*)&h0.y); a2 = fmaf(p0, f.x, a2); a3 = fmaf(p0, f.y, a3);
        f = __half22float2(*(__half2*)&h0.z); a4 = fmaf(p0, f.x, a4); a5 = fmaf(p0, f.y, a5);
        f = __half22float2(*(__half2*)&h0.w); a6 = fmaf(p0, f.x, a6); a7 = fmaf(p0, f.y, a7);
        f = __half22float2(*(__half2*)&h1.x); a0 = fmaf(p1, f.x, a0); a1 = fmaf(p1, f.y, a1);
        f = __half22float2(*(__half2*)&h1.y); a2 = fmaf(p1, f.x, a2); a3 = fmaf(p1, f.y, a3);
        f = __half22float2(*(__half2*)&h1.z); a4 = fmaf(p1, f.x, a4); a5 = fmaf(p1, f.y, a5);
        f = __half22float2(*(__half2*)&h1.w); a6 = fmaf(p1, f.x, a6); a7 = fmaf(p1, f.y, a7);
        f = __half22float2(*(__half2*)&h2.x); a0 = fmaf(p2, f.x, a0); a1 = fmaf(p2, f.y, a1);
        f = __half22float2(*(__half2*)&h2.y); a2 = fmaf(p2, f.x, a2); a3 = fmaf(p2, f.y, a3);
        f = __half22float2(*(__half2*)&h2.z); a4 = fmaf(p2, f.x, a4); a5 = fmaf(p2, f.y, a5);
        f = __half22float2(*(__half2*)&h2.w); a6 = fmaf(p2, f.x, a6); a7 = fmaf(p2, f.y, a7);
        f = __half22float2(*(__half2*)&h3.x); a0 = fmaf(p3, f.x, a0); a1 = fmaf(p3, f.y, a1);
        f = __half22float2(*(__half2*)&h3.y); a2 = fmaf(p3, f.x, a2); a3 = fmaf(p3, f.y, a3);
        f = __half22float2(*(__half2*)&h3.z); a4 = fmaf(p3, f.x, a4); a5 = fmaf(p3, f.y, a5);
        f = __half22float2(*(__half2*)&h3.w); a6 = fmaf(p3, f.x, a6); a7 = fmaf(p3, f.y, a7);
    }
    for (; j < deg; j++) {
        int s0 = __ldg(&g_csrc[rs + j]);
        uint4 h0 = __ldg(&hp[s0 * 8 + r]);
        float p0 = edge_p(s0, dval);
        s += p0;
        float2 f;
        f = __half22float2(*(__half2*)&h0.x); a0 = fmaf(p0, f.x, a0); a1 = fmaf(p0, f.y, a1);
        f = __half22float2(*(__half2*)&h0.y); a2 = fmaf(p0, f.x, a2); a3 = fmaf(p0, f.y, a3);
        f = __half22float2(*(__half2*)&h0.z); a4 = fmaf(p0, f.x, a4); a5 = fmaf(p0, f.y, a5);
        f = __half22float2(*(__half2*)&h0.w); a6 = fmaf(p0, f.x, a6); a7 = fmaf(p0, f.y, a7);
    }

    if (!valid) return;
    float inv = 1.f / (s + 1e-16f);
    float4 b0 = *(const float4*)&bias[8 * r];
    float4 b1 = *(const float4*)&bias[8 * r + 4];
    float v0 = fmaf(a0, inv, b0.x);
    float v1 = fmaf(a1, inv, b0.y);
    float v2 = fmaf(a2, inv, b0.z);
    float v3 = fmaf(a3, inv, b0.w);
    float v4 = fmaf(a4, inv, b1.x);
    float v5 = fmaf(a5, inv, b1.y);
    float v6 = fmaf(a6, inv, b1.z);
    float v7 = fmaf(a7, inv, b1.w);
    v0 = v0 > 0.f ? v0 : 0.01f * v0;
    v1 = v1 > 0.f ? v1 : 0.01f * v1;
    v2 = v2 > 0.f ? v2 : 0.01f * v2;
    v3 = v3 > 0.f ? v3 : 0.01f * v3;
    v4 = v4 > 0.f ? v4 : 0.01f * v4;
    v5 = v5 > 0.f ? v5 : 0.01f * v5;
    v6 = v6 > 0.f ? v6 : 0.01f * v6;
    v7 = v7 > 0.f ? v7 : 0.01f * v7;
    __half2 o0 = __floats2half2_rn(v0, v1);
    __half2 o1 = __floats2half2_rn(v2, v3);
    __half2 o2 = __floats2half2_rn(v4, v5);
    __half2 o3 = __floats2half2_rn(v6, v7);
    uint4 pack = make_uint4(*(unsigned*)&o0, *(unsigned*)&o1,
                            *(unsigned*)&o2, *(unsigned*)&o3);
    *(uint4*)&outp[(size_t)n * 32 + 4 * r] = pack;
}

// ---- virtual node pool: 256 threads = 4 groups x 64 cols, 64 nodes/group ----
__global__ void k_pool(const int* __restrict__ batch) {
    int c = threadIdx.x & 63;
    int grp = threadIdx.x >> 6;
    int n0 = blockIdx.x * 256 + grp * 64;
    int n1 = n0 + 64; if (n1 > NN) n1 = NN;
    if (n0 >= NN) return;
    const __half* xp = (const __half*)g_x2;
    float acc = 0.f;
    int cur = batch[n0];
    for (int n = n0; n < n1; n++) {
        int bb = batch[n];
        if (bb != cur) { atomicAdd(&g_vn[cur * DH + c], acc); acc = 0.f; cur = bb; }
        acc += __half2float(xp[(size_t)n * DH + c]);
    }
    atomicAdd(&g_vn[cur * DH + c], acc);
}

// ---- 4-layer MLP on vn, one block (64 threads) per graph ----
__global__ void k_vnmlp(const float* __restrict__ W1, const float* __restrict__ b1,
                        const float* __restrict__ W2, const float* __restrict__ b2,
                        const float* __restrict__ W3, const float* __restrict__ b3,
                        const float* __restrict__ W4, const float* __restrict__ b4,
                        float* __restrict__ outp) {
    __shared__ float r[64];
    int g = blockIdx.x, c = threadIdx.x;
    r[c] = g_vn[g * DH + c];
    __syncthreads();
    const float* Ws[4] = {W1, W2, W3, W4};
    const float* bs[4] = {b1, b2, b3, b4};
    for (int L = 0; L < 4; L++) {
        float acc = bs[L][c];
        for (int k = 0; k < 64; k++) acc = fmaf(r[k], Ws[L][k * 64 + c], acc);
        __syncthreads();
        r[c] = acc > 0.f ? acc : 0.f;
        __syncthreads();
    }
    outp[g * DH + c] = r[c];
}

extern "C" void kernel_launch(void* const* d_in, const int* in_sizes, int n_in,
                              void* d_out, int out_size) {
    const float* x     = (const float*)d_in[0];
    const int*   ei    = (const int*)d_in[1];
    const int*   batch = (const int*)d_in[2];
    int o = (in_sizes[3] <= 16) ? 4 : 3;
    const float* W[3], *asr[3], *adt[3], *bb[3];
    for (int i = 0; i < 3; i++) {
        W[i]   = (const float*)d_in[o + 4 * i + 0];
        asr[i] = (const float*)d_in[o + 4 * i + 1];
        adt[i] = (const float*)d_in[o + 4 * i + 2];
        bb[i]  = (const float*)d_in[o + 4 * i + 3];
    }
    const float* Wout = (const float*)d_in[o + 12];
    const float* bout = (const float*)d_in[o + 13];
    const float* vne  = (const float*)d_in[o + 14];
    const float* Wm1 = (const float*)d_in[o + 15], *bm1 = (const float*)d_in[o + 16];
    const float* Wm2 = (const float*)d_in[o + 17], *bm2 = (const float*)d_in[o + 18];
    const float* Wf1 = (const float*)d_in[o + 19], *bf1 = (const float*)d_in[o + 20];
    const float* Wf2 = (const float*)d_in[o + 21], *bf2 = (const float*)d_in[o + 22];

    __half2* px2 = nullptr;
    cudaGetSymbolAddress((void**)&px2, g_x2);
    float* out = (float*)d_out;

    // ---- CSR build (once; reused by all 3 layers) ----
    k_initcnt<<<(NN + 255) / 256, 256>>>(vne);
    k_hist<<<(NE + 255) / 256, 256>>>(ei);
    k_scan1<<<NB_SCAN, 1024>>>();
    k_scan3<<<(NN + 255) / 256, 256>>>();
    k_scatter<<<(ET + 255) / 256, 256>>>(ei);

    // ---- 3 GAT layers ----
    for (int L = 0; L < 3; L++) {
        const void* cur = (L == 0) ? (const void*)x : (const void*)px2;
        k_mm<<<(NN + 255) / 256, 512>>>(cur, L != 0, W[L], nullptr, nullptr, 1,
                                        asr[L], adt[L]);
        k_agg<<<(NN + 31) / 32, 256>>>(bb[L], px2);
    }

    // final node projection (fp32 out, with bias)
    k_mm<<<(NN + 255) / 256, 512>>>(px2, 1, Wout, bout, out, 0, nullptr, nullptr);

    // virtual node branch
    k_pool<<<(NN + 255) / 256, 256>>>(batch);
    k_vnmlp<<<NG, 64>>>(Wm1, bm1, Wm2, bm2, Wf1, bf1, Wf2, bf2, out + (size_t)NN * DH);
}

// round 16
// speedup vs baseline: 1.1331x; 1.0199x over previous
#include <cuda_runtime.h>
#include <cuda_fp16.h>
#include <math.h>

#define NN 100000
#define NE 1600000
#define ET (NE + NN)
#define DH 64
#define NG 64
#define NB_SCAN 98   // ceil(NN/1024)
#define XST 72       // padded smem row stride (halves) -> conflict-free frags

// ---- scratch (device globals) ----
__device__ __align__(16) __half2 g_h2[NN * 32];   // projected features (fp16)
__device__ __align__(16) __half2 g_x2[NN * 32];   // activated layer output (fp16)
__device__ float g_s[NN];                         // h . a_src per node
__device__ float g_d[NN];                         // h . a_dst per node
__device__ float g_vn[NG * DH];                   // pooled virtual-node features
__device__ int   g_cnt[NN];                       // in-degree (incl. self loop)
__device__ int   g_row[NN + 1];                   // CSR row offsets (by dst)
__device__ int   g_woff[NN];                      // working offsets for scatter
__device__ int   g_csrc[ET];                      // CSR: src node per edge slot
__device__ int   g_bsum[128];

// ===========================================================================
// CSR build (edge_index constant across layers -> build once per launch)
// ===========================================================================
__global__ void k_initcnt(const float* __restrict__ emb) {
    int i = blockIdx.x * blockDim.x + threadIdx.x;
    if (i < NN) g_cnt[i] = 1;  // self loop
    if (i < NG * DH) g_vn[i] = emb[i & 63];  // virtual-node init (fused)
}

__global__ void k_hist(const int* __restrict__ ei) {
    int i = blockIdx.x * blockDim.x + threadIdx.x;
    if (i < NE) atomicAdd(&g_cnt[ei[NE + i]], 1);
}

// warp-shuffle block scan (1024 threads)
__global__ void k_scan1() {
    __shared__ int wsum[32];
    int t = threadIdx.x;
    int idx = blockIdx.x * 1024 + t;
    int v = (idx < NN) ? g_cnt[idx] : 0;
    int lane = t & 31, wid = t >> 5;
    int sc = v;
#pragma unroll
    for (int o = 1; o < 32; o <<= 1) {
        int nv = __shfl_up_sync(0xffffffffu, sc, o);
        if (lane >= o) sc += nv;
    }
    if (lane == 31) wsum[wid] = sc;
    __syncthreads();
    if (wid == 0) {
        int wv = wsum[lane];
        int ws = wv;
#pragma unroll
        for (int o = 1; o < 32; o <<= 1) {
            int nv = __shfl_up_sync(0xffffffffu, ws, o);
            if (lane >= o) ws += nv;
        }
        wsum[lane] = ws - wv;  // exclusive
    }
    __syncthreads();
    int incl = sc + wsum[wid];
    if (idx < NN) g_row[idx] = incl - v;
    if (t == 1023) g_bsum[blockIdx.x] = incl;
}

__global__ void k_scan3() {
    __shared__ int sb[128];
    int t = threadIdx.x;
    if (t < 128) sb[t] = (t < NB_SCAN) ? g_bsum[t] : 0;
    __syncthreads();
#pragma unroll
    for (int o = 1; o < 128; o <<= 1) {
        int nv = (t >= o && t < 128) ? sb[t - o] : 0;
        __syncthreads();
        if (t < 128) sb[t] += nv;
        __syncthreads();
    }
    int idx = blockIdx.x * blockDim.x + t;
    if (idx < NN) {
        int blk = idx >> 10;
        int r = g_row[idx] + (blk ? sb[blk - 1] : 0);
        g_row[idx] = r;
        g_woff[idx] = r;
    }
    if (idx == 0) g_row[NN] = ET;
}

__global__ void k_scatter(const int* __restrict__ ei) {
    int i = blockIdx.x * blockDim.x + threadIdx.x;
    if (i >= ET) return;
    int s, d;
    if (i < NE) { s = ei[i]; d = ei[NE + i]; }
    else        { s = d = i - NE; }
    int pos = atomicAdd(&g_woff[d], 1);
    g_csrc[pos] = s;
}

// ===========================================================================
// Tensor-core matmul: 256 nodes / 512-thread block; conflict-free padded smem.
// ===========================================================================
__global__ void __launch_bounds__(512) k_mm(
        const void* __restrict__ xin, int inHalf, const float* __restrict__ W,
        const float* __restrict__ bias, float* __restrict__ dstF, int writeH,
        const float* __restrict__ a_src, const float* __restrict__ a_dst) {
    __shared__ __align__(16) __half xs[256 * XST];   // 36 KB
    __shared__ __align__(16) __half Wt[64 * XST];    // 9 KB
    __shared__ float sbias[64], sas[64], sad[64];
    int t = threadIdx.x;
    if (t < 64) {
        sbias[t] = bias  ? bias[t]  : 0.f;
        sas[t]   = a_src ? a_src[t] : 0.f;
        sad[t]   = a_dst ? a_dst[t] : 0.f;
    }
    const float4* W4 = (const float4*)W;
    for (int i4 = t; i4 < 1024; i4 += 512) {
        float4 wv = W4[i4];
        int k = i4 >> 4;
        int n0 = (i4 & 15) * 4;
        Wt[(n0 + 0) * XST + k] = __float2half(wv.x);
        Wt[(n0 + 1) * XST + k] = __float2half(wv.y);
        Wt[(n0 + 2) * XST + k] = __float2half(wv.z);
        Wt[(n0 + 3) * XST + k] = __float2half(wv.w);
    }
    int base = blockIdx.x * 256;
    if (inHalf) {
        const uint2* xh = (const uint2*)xin;
        for (int i4 = t; i4 < 4096; i4 += 512) {
            int g4 = base * 16 + i4;
            uint2 v = (g4 < NN * 16) ? __ldg(&xh[g4]) : make_uint2(0u, 0u);
            int node = i4 >> 4, c = i4 & 15;
            *(uint2*)&xs[node * XST + c * 4] = v;
        }
    } else {
        const float4* x4 = (const float4*)xin;
        for (int i4 = t; i4 < 4096; i4 += 512) {
            int g4 = base * 16 + i4;
            float4 v = (g4 < NN * 16) ? x4[g4] : make_float4(0.f, 0.f, 0.f, 0.f);
            int node = i4 >> 4, c = i4 & 15;
            __half2* d2 = (__half2*)&xs[node * XST + c * 4];
            d2[0] = __floats2half2_rn(v.x, v.y);
            d2[1] = __floats2half2_rn(v.z, v.w);
        }
    }
    __syncthreads();

    int w = t >> 5, l = t & 31;
    int gr = l >> 2, q = l & 3;
    int lrow = w * 16 + gr;      // local row in [0,256)

    float acc[8][4];
#pragma unroll
    for (int i = 0; i < 8; i++)
#pragma unroll
        for (int j = 0; j < 4; j++) acc[i][j] = 0.f;

    const unsigned* xsu = (const unsigned*)xs;
    const unsigned* wtu = (const unsigned*)Wt;
#pragma unroll
    for (int kk = 0; kk < 4; kk++) {
        int k0 = 16 * kk + 2 * q;
        unsigned a0 = xsu[(lrow * XST + k0) >> 1];
        unsigned a1 = xsu[((lrow + 8) * XST + k0) >> 1];
        unsigned a2 = xsu[(lrow * XST + k0 + 8) >> 1];
        unsigned a3 = xsu[((lrow + 8) * XST + k0 + 8) >> 1];
#pragma unroll
        for (int tt = 0; tt < 8; tt++) {
            int n = tt * 8 + gr;
            unsigned b0 = wtu[(n * XST + k0) >> 1];
            unsigned b1 = wtu[(n * XST + k0 + 8) >> 1];
            asm("mma.sync.aligned.m16n8k16.row.col.f32.f16.f16.f32 "
                "{%0,%1,%2,%3}, {%4,%5,%6,%7}, {%8,%9}, {%0,%1,%2,%3};"
                : "+f"(acc[tt][0]), "+f"(acc[tt][1]),
                  "+f"(acc[tt][2]), "+f"(acc[tt][3])
                : "r"(a0), "r"(a1), "r"(a2), "r"(a3), "r"(b0), "r"(b1));
        }
    }

    int n0 = base + lrow, n1 = n0 + 8;
    float s0 = 0.f, s1 = 0.f, d0s = 0.f, d1s = 0.f;
#pragma unroll
    for (int tt = 0; tt < 8; tt++) {
        int c0 = tt * 8 + 2 * q;
        float2 bv = *(float2*)&sbias[c0];
        float v00 = acc[tt][0] + bv.x, v01 = acc[tt][1] + bv.y;
        float v10 = acc[tt][2] + bv.x, v11 = acc[tt][3] + bv.y;
        if (writeH) {
            if (n0 < NN) g_h2[(size_t)n0 * 32 + tt * 4 + q] = __floats2half2_rn(v00, v01);
            if (n1 < NN) g_h2[(size_t)n1 * 32 + tt * 4 + q] = __floats2half2_rn(v10, v11);
        }
        if (dstF) {
            if (n0 < NN) *(float2*)&dstF[(size_t)n0 * 64 + c0] = make_float2(v00, v01);
            if (n1 < NN) *(float2*)&dstF[(size_t)n1 * 64 + c0] = make_float2(v10, v11);
        }
        if (a_src) {
            float2 asv = *(float2*)&sas[c0];
            float2 adv = *(float2*)&sad[c0];
            s0  += v00 * asv.x + v01 * asv.y;
            s1  += v10 * asv.x + v11 * asv.y;
            d0s += v00 * adv.x + v01 * adv.y;
            d1s += v10 * adv.x + v11 * adv.y;
        }
    }
    if (a_src) {
#pragma unroll
        for (int o = 1; o <= 2; o <<= 1) {
            s0  += __shfl_xor_sync(0xffffffffu, s0, o);
            s1  += __shfl_xor_sync(0xffffffffu, s1, o);
            d0s += __shfl_xor_sync(0xffffffffu, d0s, o);
            d1s += __shfl_xor_sync(0xffffffffu, d1s, o);
        }
        if (q == 0) {
            if (n0 < NN) { g_s[n0] = s0; g_d[n0] = d0s; }
            if (n1 < NN) { g_s[n1] = s1; g_d[n1] = d1s; }
        }
    }
}

// ===========================================================================
// Fused GAT softmax + aggregation; shift-free softmax.
// FOUR nodes per warp, 8 lanes/node, 8 cols (uint4)/lane.
// 8 edges in flight per node-group for latency hiding.
// ===========================================================================
__device__ __forceinline__ float edge_p(int src, float dval) {
    float e = __ldg(&g_s[src]) + dval;
    e = fmaxf(e, 0.2f * e);          // leaky_relu(0.2)
    return __expf(fminf(e, 60.f));
}

__global__ void __launch_bounds__(256, 4) k_agg(const float* __restrict__ bias,
                                                __half2* __restrict__ outp) {
    int w = threadIdx.x >> 5, lane = threadIdx.x & 31;
    int g = lane >> 3, r = lane & 7;
    int n = blockIdx.x * 32 + w * 4 + g;
    bool valid = n < NN;
    int rs = valid ? g_row[n] : 0;
    int deg = valid ? g_row[n + 1] - rs : 0;
    float dval = valid ? g_d[n] : 0.f;

    float s = 0.f;
    float a0 = 0.f, a1 = 0.f, a2 = 0.f, a3 = 0.f;
    float a4 = 0.f, a5 = 0.f, a6 = 0.f, a7 = 0.f;
    const uint4* __restrict__ hp = (const uint4*)g_h2;  // 8 uint4 per row

    int j = 0;
    for (; j + 8 <= deg; j += 8) {
        int s_[8];
#pragma unroll
        for (int u = 0; u < 8; u++) s_[u] = __ldg(&g_csrc[rs + j + u]);
        uint4 h_[8];
#pragma unroll
        for (int u = 0; u < 8; u++) h_[u] = __ldg(&hp[s_[u] * 8 + r]);
        float p_[8];
#pragma unroll
        for (int u = 0; u < 8; u++) p_[u] = edge_p(s_[u], dval);
#pragma unroll
        for (int u = 0; u < 8; u++) {
            s += p_[u];
            float2 f;
            f = __half22float2(*(__half2*)&h_[u].x); a0 = fmaf(p_[u], f.x, a0); a1 = fmaf(p_[u], f.y, a1);
            f = __half22float2(*(__half2*)&h_[u].y); a2 = fmaf(p_[u], f.x, a2); a3 = fmaf(p_[u], f.y, a3);
            f = __half22float2(*(__half2*)&h_[u].z); a4 = fmaf(p_[u], f.x, a4); a5 = fmaf(p_[u], f.y, a5);
            f = __half22float2(*(__half2*)&h_[u].w); a6 = fmaf(p_[u], f.x, a6); a7 = fmaf(p_[u], f.y, a7);
        }
    }
    for (; j < deg; j++) {
        int s0 = __ldg(&g_csrc[rs + j]);
        uint4 h0 = __ldg(&hp[s0 * 8 + r]);
        float p0 = edge_p(s0, dval);
        s += p0;
        float2 f;
        f = __half22float2(*(__half2*)&h0.x); a0 = fmaf(p0, f.x, a0); a1 = fmaf(p0, f.y, a1);
        f = __half22float2(*(__half2*)&h0.y); a2 = fmaf(p0, f.x, a2); a3 = fmaf(p0, f.y, a3);
        f = __half22float2(*(__half2*)&h0.z); a4 = fmaf(p0, f.x, a4); a5 = fmaf(p0, f.y, a5);
        f = __half22float2(*(__half2*)&h0.w); a6 = fmaf(p0, f.x, a6); a7 = fmaf(p0, f.y, a7);
    }

    if (!valid) return;
    float inv = 1.f / (s + 1e-16f);
    float4 b0 = *(const float4*)&bias[8 * r];
    float4 b1 = *(const float4*)&bias[8 * r + 4];
    float v0 = fmaf(a0, inv, b0.x);
    float v1 = fmaf(a1, inv, b0.y);
    float v2 = fmaf(a2, inv, b0.z);
    float v3 = fmaf(a3, inv, b0.w);
    float v4 = fmaf(a4, inv, b1.x);
    float v5 = fmaf(a5, inv, b1.y);
    float v6 = fmaf(a6, inv, b1.z);
    float v7 = fmaf(a7, inv, b1.w);
    v0 = v0 > 0.f ? v0 : 0.01f * v0;
    v1 = v1 > 0.f ? v1 : 0.01f * v1;
    v2 = v2 > 0.f ? v2 : 0.01f * v2;
    v3 = v3 > 0.f ? v3 : 0.01f * v3;
    v4 = v4 > 0.f ? v4 : 0.01f * v4;
    v5 = v5 > 0.f ? v5 : 0.01f * v5;
    v6 = v6 > 0.f ? v6 : 0.01f * v6;
    v7 = v7 > 0.f ? v7 : 0.01f * v7;
    __half2 o0 = __floats2half2_rn(v0, v1);
    __half2 o1 = __floats2half2_rn(v2, v3);
    __half2 o2 = __floats2half2_rn(v4, v5);
    __half2 o3 = __floats2half2_rn(v6, v7);
    uint4 pack = make_uint4(*(unsigned*)&o0, *(unsigned*)&o1,
                            *(unsigned*)&o2, *(unsigned*)&o3);
    *(uint4*)&outp[(size_t)n * 32 + 4 * r] = pack;
}

// ---- virtual node pool: 8 groups x 32 lanes, 2 cols (half2) per lane ----
__global__ void k_pool(const int* __restrict__ batch) {
    int lane = threadIdx.x & 31;
    int grp = threadIdx.x >> 5;           // 0..7
    int n0 = blockIdx.x * 256 + grp * 32;
    int n1 = n0 + 32; if (n1 > NN) n1 = NN;
    if (n0 >= NN) return;
    const __half2* xp = g_x2;
    float acc0 = 0.f, acc1 = 0.f;
    int cur = batch[n0];
    for (int n = n0; n < n1; n++) {
        int bb = batch[n];
        if (bb != cur) {
            atomicAdd(&g_vn[cur * DH + 2 * lane], acc0);
            atomicAdd(&g_vn[cur * DH + 2 * lane + 1], acc1);
            acc0 = acc1 = 0.f; cur = bb;
        }
        float2 f = __half22float2(xp[(size_t)n * 32 + lane]);
        acc0 += f.x; acc1 += f.y;
    }
    atomicAdd(&g_vn[cur * DH + 2 * lane], acc0);
    atomicAdd(&g_vn[cur * DH + 2 * lane + 1], acc1);
}

// ---- 4-layer MLP on vn, one block (64 threads) per graph ----
__global__ void k_vnmlp(const float* __restrict__ W1, const float* __restrict__ b1,
                        const float* __restrict__ W2, const float* __restrict__ b2,
                        const float* __restrict__ W3, const float* __restrict__ b3,
                        const float* __restrict__ W4, const float* __restrict__ b4,
                        float* __restrict__ outp) {
    __shared__ float r[64];
    int g = blockIdx.x, c = threadIdx.x;
    r[c] = g_vn[g * DH + c];
    __syncthreads();
    const float* Ws[4] = {W1, W2, W3, W4};
    const float* bs[4] = {b1, b2, b3, b4};
    for (int L = 0; L < 4; L++) {
        float acc = bs[L][c];
        for (int k = 0; k < 64; k++) acc = fmaf(r[k], Ws[L][k * 64 + c], acc);
        __syncthreads();
        r[c] = acc > 0.f ? acc : 0.f;
        __syncthreads();
    }
    outp[g * DH + c] = r[c];
}

extern "C" void kernel_launch(void* const* d_in, const int* in_sizes, int n_in,
                              void* d_out, int out_size) {
    const float* x     = (const float*)d_in[0];
    const int*   ei    = (const int*)d_in[1];
    const int*   batch = (const int*)d_in[2];
    int o = (in_sizes[3] <= 16) ? 4 : 3;
    const float* W[3], *asr[3], *adt[3], *bb[3];
    for (int i = 0; i < 3; i++) {
        W[i]   = (const float*)d_in[o + 4 * i + 0];
        asr[i] = (const float*)d_in[o + 4 * i + 1];
        adt[i] = (const float*)d_in[o + 4 * i + 2];
        bb[i]  = (const float*)d_in[o + 4 * i + 3];
    }
    const float* Wout = (const float*)d_in[o + 12];
    const float* bout = (const float*)d_in[o + 13];
    const float* vne  = (const float*)d_in[o + 14];
    const float* Wm1 = (const float*)d_in[o + 15], *bm1 = (const float*)d_in[o + 16];
    const float* Wm2 = (const float*)d_in[o + 17], *bm2 = (const float*)d_in[o + 18];
    const float* Wf1 = (const float*)d_in[o + 19], *bf1 = (const float*)d_in[o + 20];
    const float* Wf2 = (const float*)d_in[o + 21], *bf2 = (const float*)d_in[o + 22];

    __half2* px2 = nullptr;
    cudaGetSymbolAddress((void**)&px2, g_x2);
    float* out = (float*)d_out;

    // ---- CSR build (once; reused by all 3 layers) ----
    k_initcnt<<<(NN + 255) / 256, 256>>>(vne);
    k_hist<<<(NE + 255) / 256, 256>>>(ei);
    k_scan1<<<NB_SCAN, 1024>>>();
    k_scan3<<<(NN + 255) / 256, 256>>>();
    k_scatter<<<(ET + 255) / 256, 256>>>(ei);

    // ---- 3 GAT layers ----
    for (int L = 0; L < 3; L++) {
        const void* cur = (L == 0) ? (const void*)x : (const void*)px2;
        k_mm<<<(NN + 255) / 256, 512>>>(cur, L != 0, W[L], nullptr, nullptr, 1,
                                        asr[L], adt[L]);
        k_agg<<<(NN + 31) / 32, 256>>>(bb[L], px2);
    }

    // final node projection (fp32 out, with bias)
    k_mm<<<(NN + 255) / 256, 512>>>(px2, 1, Wout, bout, out, 0, nullptr, nullptr);

    // virtual node branch
    k_pool<<<(NN + 255) / 256, 256>>>(batch);
    k_vnmlp<<<NG, 64>>>(Wm1, bm1, Wm2, bm2, Wf1, bf1, Wf2, bf2, out + (size_t)NN * DH);
}